// round 1
// baseline (speedup 1.0000x reference)
#include <cuda_runtime.h>
#include <cuda_bf16.h>

// Problem constants
#define BB 8
#define NN 512
#define SS 96
#define HH 256
#define NHH 8
#define HDD 32
#define OUTD 4
#define MQ (BB*NN)   // 4096
#define MK (BB*SS)   // 768

// Scratch (device globals — no allocation allowed)
__device__ float g_sp[MQ*HH];
__device__ float g_tp[MK*HH];
__device__ float g_q [MQ*HH];
__device__ float g_k [MK*HH];
__device__ float g_v [MK*HH];
__device__ float g_ctx[MQ*HH];
__device__ float g_att[MQ*HH];
__device__ float g_fu [MQ*HH];
__device__ float g_h2 [MQ*(HH/2)];
__device__ float g_y  [MQ*OUTD];

// ---------------------------------------------------------------------------
// Generic NT GEMM: C[m,n] = sum_k A[m,k] * W[n,k] + bias[n]  (optional ReLU)
// A: (M,K) row-major, W: (N,K) row-major. M % 64 == 0, N % 64 == 0, K % 16 == 0.
// Block: 256 threads. Tile 64x64, k-tile 16, 4x4 per thread.
// ---------------------------------------------------------------------------
template<int RELU>
__global__ void __launch_bounds__(256) gemm_nt(
    const float* __restrict__ A, const float* __restrict__ W,
    const float* __restrict__ bias, float* __restrict__ C,
    int M, int N, int K)
{
    __shared__ float As[16][65];
    __shared__ float Bs[16][65];
    const int n0 = blockIdx.x * 64;
    const int m0 = blockIdx.y * 64;
    const int tid = threadIdx.x;
    const int tx = tid & 15;        // n sub-tile
    const int ty = tid >> 4;        // m sub-tile
    float acc[4][4] = {};

    for (int k0 = 0; k0 < K; k0 += 16) {
        #pragma unroll
        for (int i = 0; i < 4; i++) {
            int idx = tid + i * 256;          // 0..1023
            int r = idx >> 4;                 // 0..63
            int c = idx & 15;                 // 0..15
            As[c][r] = A[(m0 + r) * K + k0 + c];
            Bs[c][r] = W[(n0 + r) * K + k0 + c];
        }
        __syncthreads();
        #pragma unroll
        for (int kk = 0; kk < 16; kk++) {
            float a[4], b[4];
            #pragma unroll
            for (int i = 0; i < 4; i++) a[i] = As[kk][ty * 4 + i];
            #pragma unroll
            for (int j = 0; j < 4; j++) b[j] = Bs[kk][tx * 4 + j];
            #pragma unroll
            for (int i = 0; i < 4; i++)
                #pragma unroll
                for (int j = 0; j < 4; j++)
                    acc[i][j] += a[i] * b[j];
        }
        __syncthreads();
    }

    #pragma unroll
    for (int i = 0; i < 4; i++) {
        int m = m0 + ty * 4 + i;
        #pragma unroll
        for (int j = 0; j < 4; j++) {
            int n = n0 + tx * 4 + j;
            float v = acc[i][j] + bias[n];
            if (RELU) v = fmaxf(v, 0.0f);
            C[m * N + n] = v;
        }
    }
}

// ---------------------------------------------------------------------------
// Attention: per (b,h) block loads K/V head tiles into smem; warp-per-query.
// grid: (B*NH, N/128), block 128 threads (4 warps).
// q,k,v laid out (rows, 256) with head h occupying cols [h*32, h*32+32).
// ---------------------------------------------------------------------------
__global__ void __launch_bounds__(128) attn_kernel(
    const float* __restrict__ q, const float* __restrict__ k,
    const float* __restrict__ v, float* __restrict__ ctx)
{
    __shared__ float ks[SS][33];
    __shared__ float vs[SS][33];
    __shared__ float attn[4][SS];

    const int b = blockIdx.x >> 3;
    const int h = blockIdx.x & 7;
    const int n0 = blockIdx.y * 128;
    const int tid = threadIdx.x;
    const int w = tid >> 5;
    const int lane = tid & 31;

    for (int idx = tid; idx < SS * 32; idx += 128) {
        int s = idx >> 5, d = idx & 31;
        int src = (b * SS + s) * HH + h * HDD + d;
        ks[s][d] = k[src];
        vs[s][d] = v[src];
    }
    __syncthreads();

    const float scale = 0.17677669529663687f;  // 1/sqrt(32)

    for (int nl = w; nl < 128; nl += 4) {
        const int row = b * NN + n0 + nl;
        float qd = q[row * HH + h * HDD + lane] * scale;

        float acc0 = 0.f, acc1 = 0.f, acc2 = 0.f;
        #pragma unroll
        for (int d = 0; d < 32; d++) {
            float qv = __shfl_sync(0xffffffffu, qd, d);
            acc0 += qv * ks[lane][d];
            acc1 += qv * ks[lane + 32][d];
            acc2 += qv * ks[lane + 64][d];
        }
        float m = fmaxf(acc0, fmaxf(acc1, acc2));
        #pragma unroll
        for (int o = 16; o; o >>= 1) m = fmaxf(m, __shfl_xor_sync(0xffffffffu, m, o));
        float e0 = __expf(acc0 - m);
        float e1 = __expf(acc1 - m);
        float e2 = __expf(acc2 - m);
        float sum = e0 + e1 + e2;
        #pragma unroll
        for (int o = 16; o; o >>= 1) sum += __shfl_xor_sync(0xffffffffu, sum, o);
        float inv = 1.0f / sum;

        attn[w][lane]      = e0 * inv;
        attn[w][lane + 32] = e1 * inv;
        attn[w][lane + 64] = e2 * inv;
        __syncwarp();

        float cd = 0.f;
        #pragma unroll 8
        for (int s = 0; s < SS; s++) cd += attn[w][s] * vs[s][lane];
        ctx[row * HH + h * HDD + lane] = cd;
        __syncwarp();   // protect attn before next iteration's writes
    }
}

// ---------------------------------------------------------------------------
// y = h2 @ Wo2.T + bo2 : (4096,4), K=128. One thread per (row, o).
// ---------------------------------------------------------------------------
__global__ void __launch_bounds__(256) y_kernel(
    const float* __restrict__ h2, const float* __restrict__ Wo2,
    const float* __restrict__ bo2, float* __restrict__ y)
{
    int idx = blockIdx.x * 256 + threadIdx.x;
    if (idx >= MQ * OUTD) return;
    int row = idx >> 2, o = idx & 3;
    const float* hr = h2 + row * (HH / 2);
    const float* wr = Wo2 + o * (HH / 2);
    float acc = bo2[o];
    #pragma unroll 8
    for (int kk = 0; kk < HH / 2; kk++) acc += hr[kk] * wr[kk];
    y[idx] = acc;
}

// ---------------------------------------------------------------------------
// Broadcast y[b,n,o] to out[b,s,n,o]. Fully coalesced writes; y fits in L2.
// ---------------------------------------------------------------------------
__global__ void __launch_bounds__(256) bcast_kernel(
    const float* __restrict__ y, float* __restrict__ out)
{
    int idx = blockIdx.x * 256 + threadIdx.x;
    if (idx >= BB * SS * NN * OUTD) return;
    int o = idx & 3;
    int n = (idx >> 2) & (NN - 1);
    int bs = idx >> 11;            // (b*S + s)
    int b = bs / SS;
    out[idx] = y[(b * NN + n) * OUTD + o];
}

extern "C" void kernel_launch(void* const* d_in, const int* in_sizes, int n_in,
                              void* d_out, int out_size)
{
    const float* spatial  = (const float*)d_in[0];
    const float* temporal = (const float*)d_in[1];
    const float* Ws  = (const float*)d_in[2];
    const float* bs  = (const float*)d_in[3];
    const float* Wt  = (const float*)d_in[4];
    const float* bt  = (const float*)d_in[5];
    const float* Win = (const float*)d_in[6];
    const float* bin = (const float*)d_in[7];
    const float* Wao = (const float*)d_in[8];
    const float* bao = (const float*)d_in[9];
    const float* W1  = (const float*)d_in[10];
    const float* b1  = (const float*)d_in[11];
    const float* Wo1 = (const float*)d_in[12];
    const float* bo1 = (const float*)d_in[13];
    const float* Wo2 = (const float*)d_in[14];
    const float* bo2 = (const float*)d_in[15];
    float* out = (float*)d_out;

    float *sp, *tp, *qb, *kb, *vb, *ctx, *att, *fu, *h2, *y;
    cudaGetSymbolAddress((void**)&sp,  g_sp);
    cudaGetSymbolAddress((void**)&tp,  g_tp);
    cudaGetSymbolAddress((void**)&qb,  g_q);
    cudaGetSymbolAddress((void**)&kb,  g_k);
    cudaGetSymbolAddress((void**)&vb,  g_v);
    cudaGetSymbolAddress((void**)&ctx, g_ctx);
    cudaGetSymbolAddress((void**)&att, g_att);
    cudaGetSymbolAddress((void**)&fu,  g_fu);
    cudaGetSymbolAddress((void**)&h2,  g_h2);
    cudaGetSymbolAddress((void**)&y,   g_y);

    // Projections
    gemm_nt<0><<<dim3(HH/64, MQ/64), 256>>>(spatial,  Ws, bs, sp, MQ, HH, HH);
    gemm_nt<0><<<dim3(HH/64, MK/64), 256>>>(temporal, Wt, bt, tp, MK, HH, HH);

    // QKV
    gemm_nt<0><<<dim3(HH/64, MQ/64), 256>>>(sp, Win,              bin,          qb, MQ, HH, HH);
    gemm_nt<0><<<dim3(HH/64, MK/64), 256>>>(tp, Win + HH*HH,      bin + HH,     kb, MK, HH, HH);
    gemm_nt<0><<<dim3(HH/64, MK/64), 256>>>(tp, Win + 2*HH*HH,    bin + 2*HH,   vb, MK, HH, HH);

    // Attention
    attn_kernel<<<dim3(BB*NHH, NN/128), 128>>>(qb, kb, vb, ctx);

    // MLP head
    gemm_nt<0><<<dim3(HH/64,     MQ/64), 256>>>(ctx, Wao, bao, att, MQ, HH,   HH);
    gemm_nt<1><<<dim3(HH/64,     MQ/64), 256>>>(att, W1,  b1,  fu,  MQ, HH,   HH);
    gemm_nt<1><<<dim3((HH/2)/64, MQ/64), 256>>>(fu,  Wo1, bo1, h2,  MQ, HH/2, HH);

    // Tiny output GEMM + broadcast
    y_kernel<<<(MQ*OUTD + 255)/256, 256>>>(h2, Wo2, bo2, y);
    bcast_kernel<<<(BB*SS*NN*OUTD + 255)/256, 256>>>(y, out);
}

// round 4
// speedup vs baseline: 1.4766x; 1.4766x over previous
#include <cuda_runtime.h>
#include <cuda_bf16.h>

// Problem constants
#define BB 8
#define NN 512
#define SS 96
#define HH 256
#define NHH 8
#define HDD 32
#define OUTD 4
#define MQ (BB*NN)   // 4096
#define MK (BB*SS)   // 768

// Scratch (device globals — no allocation allowed)
__device__ float g_Wqp[HH*HH];   // Wq @ Ws
__device__ float g_bqp[HH];
__device__ float g_W1p[HH*HH];   // W1 @ Wao
__device__ float g_b1p[HH];
__device__ float g_tp[MK*HH];
__device__ float g_q [MQ*HH];
__device__ float g_k [MK*HH];
__device__ float g_v [MK*HH];
__device__ float g_ctx[MQ*HH];
__device__ float g_fu [MQ*HH];
__device__ float g_h2 [MQ*(HH/2)];
__device__ float g_y  [MQ*OUTD];

// ---------------------------------------------------------------------------
// NT GEMM: C[m,n] = sum_k A[m,k] * W[n,k] + bias[n]  (optional ReLU, split C)
// A: (M,K) rm, W: (N,K) rm. M%64==0, N%64==0, K%16==0.
// 256 thr, 64x64 tile, BK=16, 4x4 micro, double-buffered smem, float4 paths.
// SPLIT: cols [0,256) -> C0, [256,512) -> C1 (both stride 256).
// ---------------------------------------------------------------------------
template<int RELU, int SPLIT>
__global__ void __launch_bounds__(256) gemm_nt(
    const float* __restrict__ A, const float* __restrict__ W,
    const float* __restrict__ bias, float* __restrict__ C0,
    float* __restrict__ C1, int M, int N, int K)
{
    __shared__ __align__(16) float As[2][16][68];
    __shared__ __align__(16) float Bs[2][16][68];
    const int n0 = blockIdx.x * 64;
    const int m0 = blockIdx.y * 64;
    const int tid = threadIdx.x;
    const int tx = tid & 15;          // n micro
    const int ty = tid >> 4;          // m micro
    const int lr = tid >> 2;          // 0..63: row loaded by this thread
    const int lc = (tid & 3) * 4;     // 0,4,8,12: k offset

    const float* Ap = A + (m0 + lr) * K + lc;
    const float* Wp = W + (n0 + lr) * K + lc;

    float4 af = *(const float4*)Ap;
    float4 bf = *(const float4*)Wp;
    float acc[4][4] = {};

    As[0][lc+0][lr] = af.x; As[0][lc+1][lr] = af.y;
    As[0][lc+2][lr] = af.z; As[0][lc+3][lr] = af.w;
    Bs[0][lc+0][lr] = bf.x; Bs[0][lc+1][lr] = bf.y;
    Bs[0][lc+2][lr] = bf.z; Bs[0][lc+3][lr] = bf.w;
    __syncthreads();

    const int ktiles = K >> 4;
    int buf = 0;
    for (int t = 0; t < ktiles; t++) {
        if (t + 1 < ktiles) {
            af = *(const float4*)(Ap + (t + 1) * 16);
            bf = *(const float4*)(Wp + (t + 1) * 16);
        }
        #pragma unroll
        for (int kk = 0; kk < 16; kk++) {
            float4 a4 = *(const float4*)(&As[buf][kk][ty * 4]);
            float4 b4 = *(const float4*)(&Bs[buf][kk][tx * 4]);
            float ar[4] = {a4.x, a4.y, a4.z, a4.w};
            float br[4] = {b4.x, b4.y, b4.z, b4.w};
            #pragma unroll
            for (int i = 0; i < 4; i++)
                #pragma unroll
                for (int j = 0; j < 4; j++)
                    acc[i][j] += ar[i] * br[j];
        }
        if (t + 1 < ktiles) {
            int nb = buf ^ 1;
            As[nb][lc+0][lr] = af.x; As[nb][lc+1][lr] = af.y;
            As[nb][lc+2][lr] = af.z; As[nb][lc+3][lr] = af.w;
            Bs[nb][lc+0][lr] = bf.x; Bs[nb][lc+1][lr] = bf.y;
            Bs[nb][lc+2][lr] = bf.z; Bs[nb][lc+3][lr] = bf.w;
            __syncthreads();
            buf = nb;
        }
    }

    #pragma unroll
    for (int i = 0; i < 4; i++) {
        int m = m0 + ty * 4 + i;
        #pragma unroll
        for (int j = 0; j < 4; j++) {
            int n = n0 + tx * 4 + j;
            float v = acc[i][j] + bias[n];
            if (RELU) v = fmaxf(v, 0.0f);
            if (SPLIT) {
                if (n < 256) C0[m * 256 + n] = v;
                else         C1[m * 256 + n - 256] = v;
            } else {
                C0[m * N + n] = v;
            }
        }
    }
}

// ---------------------------------------------------------------------------
// Weight/bias combine: Wq' = Wq@Ws, W1' = W1@Wao (NN, 256x256x256 each),
// bq' = Wq@bs+bq, b1' = W1@bao+b1. Grid = 33 blocks (16+16 tiles + 1 bias).
// ---------------------------------------------------------------------------
__global__ void __launch_bounds__(256) combine_kernel(
    const float* __restrict__ Wq, const float* __restrict__ Ws,
    const float* __restrict__ bq, const float* __restrict__ bsv,
    const float* __restrict__ W1, const float* __restrict__ Wao,
    const float* __restrict__ b1, const float* __restrict__ bao,
    float* __restrict__ Wqp, float* __restrict__ bqp,
    float* __restrict__ W1p, float* __restrict__ b1p)
{
    const int bid = blockIdx.x;
    if (bid == 32) {
        int i = threadIdx.x;
        if (i < HH) {
            float a0 = bq[i], a1 = b1[i];
            const float* r0 = Wq + i * HH;
            const float* r1 = W1 + i * HH;
            #pragma unroll 8
            for (int k = 0; k < HH; k++) {
                a0 += r0[k] * bsv[k];
                a1 += r1[k] * bao[k];
            }
            bqp[i] = a0;
            b1p[i] = a1;
        }
        return;
    }
    const float* Am = (bid < 16) ? Wq : W1;
    const float* Bm = (bid < 16) ? Ws : Wao;
    float*       Cm = (bid < 16) ? Wqp : W1p;
    const int lb = bid & 15;
    const int m0 = (lb >> 2) * 64;
    const int n0 = (lb & 3) * 64;

    __shared__ __align__(16) float As[16][68];
    __shared__ __align__(16) float Bsm[16][68];
    const int tid = threadIdx.x;
    const int tx = tid & 15;
    const int ty = tid >> 4;
    const int lr = tid >> 2;
    const int lc = (tid & 3) * 4;
    const int br = tid >> 4;          // 0..15 (k row of B tile)
    const int bc = (tid & 15) * 4;    // 0..60

    float acc[4][4] = {};
    for (int k0 = 0; k0 < HH; k0 += 16) {
        float4 af = *(const float4*)(Am + (m0 + lr) * HH + k0 + lc);
        float4 bf = *(const float4*)(Bm + (k0 + br) * HH + n0 + bc);
        As[lc+0][lr] = af.x; As[lc+1][lr] = af.y;
        As[lc+2][lr] = af.z; As[lc+3][lr] = af.w;
        *(float4*)(&Bsm[br][bc]) = bf;
        __syncthreads();
        #pragma unroll
        for (int kk = 0; kk < 16; kk++) {
            float4 a4 = *(const float4*)(&As[kk][ty * 4]);
            float4 b4 = *(const float4*)(&Bsm[kk][tx * 4]);
            float ar[4] = {a4.x, a4.y, a4.z, a4.w};
            float brr[4] = {b4.x, b4.y, b4.z, b4.w};
            #pragma unroll
            for (int i = 0; i < 4; i++)
                #pragma unroll
                for (int j = 0; j < 4; j++)
                    acc[i][j] += ar[i] * brr[j];
        }
        __syncthreads();
    }
    #pragma unroll
    for (int i = 0; i < 4; i++)
        #pragma unroll
        for (int j = 0; j < 4; j++)
            Cm[(m0 + ty * 4 + i) * HH + n0 + tx * 4 + j] = acc[i][j];
}

// ---------------------------------------------------------------------------
// Attention: per (b,h) block loads K/V head tiles into smem; warp-per-query.
// ---------------------------------------------------------------------------
__global__ void __launch_bounds__(128) attn_kernel(
    const float* __restrict__ q, const float* __restrict__ k,
    const float* __restrict__ v, float* __restrict__ ctx)
{
    __shared__ float ks[SS][33];
    __shared__ float vs[SS][33];
    __shared__ float attn[4][SS];

    const int b = blockIdx.x >> 3;
    const int h = blockIdx.x & 7;
    const int n0 = blockIdx.y * 128;
    const int tid = threadIdx.x;
    const int w = tid >> 5;
    const int lane = tid & 31;

    for (int idx = tid; idx < SS * 32; idx += 128) {
        int s = idx >> 5, d = idx & 31;
        int src = (b * SS + s) * HH + h * HDD + d;
        ks[s][d] = k[src];
        vs[s][d] = v[src];
    }
    __syncthreads();

    const float scale = 0.17677669529663687f;  // 1/sqrt(32)

    for (int nl = w; nl < 128; nl += 4) {
        const int row = b * NN + n0 + nl;
        float qd = q[row * HH + h * HDD + lane] * scale;

        float acc0 = 0.f, acc1 = 0.f, acc2 = 0.f;
        #pragma unroll
        for (int d = 0; d < 32; d++) {
            float qv = __shfl_sync(0xffffffffu, qd, d);
            acc0 += qv * ks[lane][d];
            acc1 += qv * ks[lane + 32][d];
            acc2 += qv * ks[lane + 64][d];
        }
        float m = fmaxf(acc0, fmaxf(acc1, acc2));
        #pragma unroll
        for (int o = 16; o; o >>= 1) m = fmaxf(m, __shfl_xor_sync(0xffffffffu, m, o));
        float e0 = __expf(acc0 - m);
        float e1 = __expf(acc1 - m);
        float e2 = __expf(acc2 - m);
        float sum = e0 + e1 + e2;
        #pragma unroll
        for (int o = 16; o; o >>= 1) sum += __shfl_xor_sync(0xffffffffu, sum, o);
        float inv = 1.0f / sum;

        attn[w][lane]      = e0 * inv;
        attn[w][lane + 32] = e1 * inv;
        attn[w][lane + 64] = e2 * inv;
        __syncwarp();

        float cd = 0.f;
        #pragma unroll 8
        for (int s = 0; s < SS; s++) cd += attn[w][s] * vs[s][lane];
        ctx[row * HH + h * HDD + lane] = cd;
        __syncwarp();
    }
}

// ---------------------------------------------------------------------------
// y = h2 @ Wo2.T + bo2 : (4096,4), K=128.
// ---------------------------------------------------------------------------
__global__ void __launch_bounds__(256) y_kernel(
    const float* __restrict__ h2, const float* __restrict__ Wo2,
    const float* __restrict__ bo2, float* __restrict__ y)
{
    int idx = blockIdx.x * 256 + threadIdx.x;
    if (idx >= MQ * OUTD) return;
    int row = idx >> 2, o = idx & 3;
    const float4* hr = (const float4*)(h2 + row * (HH / 2));
    const float4* wr = (const float4*)(Wo2 + o * (HH / 2));
    float acc = bo2[o];
    #pragma unroll 8
    for (int kk = 0; kk < HH / 8; kk++) {
        float4 hv = hr[kk], wv = wr[kk];
        acc += hv.x * wv.x + hv.y * wv.y + hv.z * wv.z + hv.w * wv.w;
    }
    y[idx] = acc;
}

// ---------------------------------------------------------------------------
// Broadcast y[b,n,:4] to out[b,s,n,:4] as float4 writes.
// ---------------------------------------------------------------------------
__global__ void __launch_bounds__(256) bcast_kernel(
    const float4* __restrict__ y4, float4* __restrict__ out4)
{
    int idx = blockIdx.x * 256 + threadIdx.x;   // over B*S*N
    if (idx >= BB * SS * NN) return;
    int n = idx & (NN - 1);
    int bs = idx >> 9;
    int b = bs / SS;
    out4[idx] = y4[b * NN + n];
}

extern "C" void kernel_launch(void* const* d_in, const int* in_sizes, int n_in,
                              void* d_out, int out_size)
{
    const float* spatial  = (const float*)d_in[0];
    const float* temporal = (const float*)d_in[1];
    const float* Ws  = (const float*)d_in[2];
    const float* bs  = (const float*)d_in[3];
    const float* Wt  = (const float*)d_in[4];
    const float* bt  = (const float*)d_in[5];
    const float* Win = (const float*)d_in[6];
    const float* bin = (const float*)d_in[7];
    const float* Wao = (const float*)d_in[8];
    const float* bao = (const float*)d_in[9];
    const float* W1  = (const float*)d_in[10];
    const float* b1  = (const float*)d_in[11];
    const float* Wo1 = (const float*)d_in[12];
    const float* bo1 = (const float*)d_in[13];
    const float* Wo2 = (const float*)d_in[14];
    const float* bo2 = (const float*)d_in[15];
    float* out = (float*)d_out;

    float *Wqp, *bqp, *W1p, *b1p, *tp, *qb, *kb, *vb, *ctx, *fu, *h2, *y;
    cudaGetSymbolAddress((void**)&Wqp, g_Wqp);
    cudaGetSymbolAddress((void**)&bqp, g_bqp);
    cudaGetSymbolAddress((void**)&W1p, g_W1p);
    cudaGetSymbolAddress((void**)&b1p, g_b1p);
    cudaGetSymbolAddress((void**)&tp,  g_tp);
    cudaGetSymbolAddress((void**)&qb,  g_q);
    cudaGetSymbolAddress((void**)&kb,  g_k);
    cudaGetSymbolAddress((void**)&vb,  g_v);
    cudaGetSymbolAddress((void**)&ctx, g_ctx);
    cudaGetSymbolAddress((void**)&fu,  g_fu);
    cudaGetSymbolAddress((void**)&h2,  g_h2);
    cudaGetSymbolAddress((void**)&y,   g_y);

    // Fold linear-linear chains: Wq' = Wq@Ws, W1' = W1@Wao (+ biases)
    combine_kernel<<<33, 256>>>(Win, Ws, bin, bs, W1, Wao, b1, bao,
                                Wqp, bqp, W1p, b1p);

    // tp = temporal @ Wt.T + bt  (768 x 256)
    gemm_nt<0,0><<<dim3(HH/64, MK/64), 256>>>(temporal, Wt, bt, tp, nullptr, MK, HH, HH);

    // k|v = tp @ Win[H:3H].T + bin[H:3H]  (768 x 512 -> split k,v)
    gemm_nt<0,1><<<dim3(2*HH/64, MK/64), 256>>>(tp, Win + HH*HH, bin + HH, kb, vb, MK, 2*HH, HH);

    // q = spatial @ Wq'.T + bq'  (4096 x 256)
    gemm_nt<0,0><<<dim3(HH/64, MQ/64), 256>>>(spatial, Wqp, bqp, qb, nullptr, MQ, HH, HH);

    // attention -> ctx
    attn_kernel<<<dim3(BB*NHH, NN/128), 128>>>(qb, kb, vb, ctx);

    // fused = relu(ctx @ W1'.T + b1')  (4096 x 256)
    gemm_nt<1,0><<<dim3(HH/64, MQ/64), 256>>>(ctx, W1p, b1p, fu, nullptr, MQ, HH, HH);

    // h2 = relu(fused @ Wo1.T + bo1)  (4096 x 128)
    gemm_nt<1,0><<<dim3((HH/2)/64, MQ/64), 256>>>(fu, Wo1, bo1, h2, nullptr, MQ, HH/2, HH);

    // y = h2 @ Wo2.T + bo2, then broadcast
    y_kernel<<<(MQ*OUTD + 255)/256, 256>>>(h2, Wo2, bo2, y);
    bcast_kernel<<<(BB*SS*NN + 255)/256, 256>>>((const float4*)y, (float4*)out);
}